// round 2
// baseline (speedup 1.0000x reference)
#include <cuda_runtime.h>
#include <cuda_bf16.h>
#include <math.h>

// ContrastiveLoss: N=8192 points, D=64, labels int32 in [0,8).
// loss = [ sum_{same-label,i!=j} d2  +  sum_{diff-label} max(1-d,0)^2 ] / (N*(N-1))
//
// Strategy:
//   pos term: exact closed form per class: sum d2 = 2*n_c*S2_c - 2*|S1_c|^2   (O(N*D))
//   neg term: nonzero only when d < 1. Partial distance over first 8 dims is an
//             exact LOWER bound on d2 -> screen all pairs on 8 dims, exact-evaluate
//             rare survivors on all 64 dims. Overflow-safe fallback kernel included.

#define N_PTS 8192
#define NDIM 64
#define NCLS 8
#define CAP  (1 << 23)   // 8M survivor slots (expected ~3K)

__device__ float  g_S1[NCLS * NDIM];   // per-class vector sums
__device__ float  g_S2d[NCLS * NDIM];  // per-class, per-dim sum of squares
__device__ int    g_count;
__device__ int    g_overflow;
__device__ double g_neg;
__device__ int2   g_pairs[CAP];

__global__ void zero_kernel() {
    int t = threadIdx.x;
    for (int k = t; k < NCLS * NDIM; k += blockDim.x) { g_S1[k] = 0.0f; g_S2d[k] = 0.0f; }
    if (t == 0) { g_count = 0; g_overflow = 0; g_neg = 0.0; }
}

// ---------------- positive term: per-class sums ----------------
// grid: 64 blocks x 64 threads. Block b handles rows [b*128, b*128+128).
// Thread k owns dimension k; accumulates per-class partials in registers.
__global__ void pos_kernel(const float* __restrict__ X, const int* __restrict__ lab) {
    int k  = threadIdx.x;            // dim 0..63
    int r0 = blockIdx.x * 128;
    __shared__ int slab[128];
    for (int r = threadIdx.x; r < 128; r += blockDim.x)
        slab[r] = lab[r0 + r];
    __syncthreads();

    float a1[NCLS], a2[NCLS];
#pragma unroll
    for (int c = 0; c < NCLS; c++) { a1[c] = 0.0f; a2[c] = 0.0f; }

    for (int rr = 0; rr < 128; ++rr) {
        float v  = X[(r0 + rr) * NDIM + k];
        float v2 = v * v;
        int   c  = slab[rr];
#pragma unroll
        for (int cc = 0; cc < NCLS; cc++) {
            bool m = (cc == c);
            a1[cc] += m ? v  : 0.0f;
            a2[cc] += m ? v2 : 0.0f;
        }
    }
#pragma unroll
    for (int cc = 0; cc < NCLS; cc++) {
        atomicAdd(&g_S1[cc * NDIM + k], a1[cc]);
        atomicAdd(&g_S2d[cc * NDIM + k], a2[cc]);
    }
}

// ---------------- screening: 8-dim partial distance lower bound ----------------
__device__ __forceinline__ float pd8(float4 a0, float4 a1, float4 b0, float4 b1) {
    float d = a0.x - b0.x; float s = d * d;
    d = a0.y - b0.y; s = fmaf(d, d, s);
    d = a0.z - b0.z; s = fmaf(d, d, s);
    d = a0.w - b0.w; s = fmaf(d, d, s);
    d = a1.x - b1.x; s = fmaf(d, d, s);
    d = a1.y - b1.y; s = fmaf(d, d, s);
    d = a1.z - b1.z; s = fmaf(d, d, s);
    d = a1.w - b1.w; s = fmaf(d, d, s);
    return s;
}

// grid (64, 64), 128 threads. Upper-triangular block pairs only (bj >= bi).
// Each thread owns one i-row (first 8 dims in regs), loops over 128 j-rows in smem.
__global__ void __launch_bounds__(128) screen_kernel(const float* __restrict__ X) {
    int bi = blockIdx.y, bj = blockIdx.x;
    if (bj < bi) return;
    int t = threadIdx.x;
    int i = bi * 128 + t;

    __shared__ float4 sj[128][2];
    const float4* Xv = (const float4*)X;   // row r -> Xv[r*16 + 0..15]; first 8 floats = [0],[1]
    int jr = bj * 128 + t;
    sj[t][0] = Xv[jr * 16 + 0];
    sj[t][1] = Xv[jr * 16 + 1];
    float4 a0 = Xv[i * 16 + 0];
    float4 a1 = Xv[i * 16 + 1];
    __syncthreads();

    bool diag = (bi == bj);
#pragma unroll 4
    for (int j = 0; j < 128; ++j) {
        float4 b0 = sj[j][0];
        float4 b1 = sj[j][1];
        float  s  = pd8(a0, a1, b0, b1);
        // exact lower bound on d2; push if could be < 1 (small fp slack)
        if (s < 1.001f && (!diag || j > t)) {
            int idx = atomicAdd(&g_count, 1);
            if (idx < CAP) g_pairs[idx] = make_int2(i, bj * 128 + j);
            else           g_overflow = 1;
        }
    }
}

// ---------------- stage 2: exact evaluation of survivors ----------------
__global__ void stage2_kernel(const float* __restrict__ X, const int* __restrict__ lab) {
    if (g_overflow) return;   // fallback kernel handles everything instead
    int n = g_count; if (n > CAP) n = CAP;
    int stride = gridDim.x * blockDim.x;
    for (int idx = blockIdx.x * blockDim.x + threadIdx.x; idx < n; idx += stride) {
        int2 p = g_pairs[idx];
        if (lab[p.x] == lab[p.y]) continue;   // pos handled in closed form
        const float4* xi = (const float4*)(X + p.x * NDIM);
        const float4* xj = (const float4*)(X + p.y * NDIM);
        float s = 0.0f;
#pragma unroll
        for (int q = 0; q < 16; q++) {
            float4 a = xi[q], b = xj[q];
            float d;
            d = a.x - b.x; s = fmaf(d, d, s);
            d = a.y - b.y; s = fmaf(d, d, s);
            d = a.z - b.z; s = fmaf(d, d, s);
            d = a.w - b.w; s = fmaf(d, d, s);
        }
        if (s < 1.0f) {
            float u = 1.0f - sqrtf(fmaxf(s, 0.0f));
            atomicAdd(&g_neg, 2.0 * (double)u * (double)u);   // x2: unordered -> ordered pairs
        }
    }
}

// ---------------- overflow fallback: brute-force neg term ----------------
__global__ void fallback_kernel(const float* __restrict__ X, const int* __restrict__ lab) {
    if (!g_overflow) return;
    const long long TOT = (long long)N_PTS * N_PTS;
    long long stride = (long long)gridDim.x * blockDim.x;
    double acc = 0.0;
    for (long long t = (long long)blockIdx.x * blockDim.x + threadIdx.x; t < TOT; t += stride) {
        int i = (int)(t >> 13);
        int j = (int)(t & (N_PTS - 1));
        if (j <= i) continue;
        if (lab[i] == lab[j]) continue;
        const float* xi = X + i * NDIM;
        const float* xj = X + j * NDIM;
        float s = 0.0f;
        for (int k = 0; k < NDIM; k++) { float d = xi[k] - xj[k]; s = fmaf(d, d, s); }
        if (s < 1.0f) { float u = 1.0f - sqrtf(s); acc += 2.0 * (double)u * (double)u; }
    }
    if (acc != 0.0) atomicAdd(&g_neg, acc);
}

// ---------------- finalize ----------------
__global__ void finalize_kernel(const int* __restrict__ lab, float* __restrict__ out) {
    __shared__ int hist[NCLS];
    int t = threadIdx.x;
    if (t < NCLS) hist[t] = 0;
    __syncthreads();
    for (int r = t; r < N_PTS; r += blockDim.x)
        atomicAdd(&hist[lab[r]], 1);
    __syncthreads();
    if (t == 0) {
        double pos = 0.0;
        for (int c = 0; c < NCLS; c++) {
            double S2 = 0.0, dot = 0.0;
            for (int k = 0; k < NDIM; k++) {
                double v = (double)g_S1[c * NDIM + k];
                dot += v * v;
                S2  += (double)g_S2d[c * NDIM + k];
            }
            pos += 2.0 * ((double)hist[c] * S2 - dot);
        }
        double loss = (pos + g_neg) / ((double)N_PTS * (double)(N_PTS - 1));
        out[0] = (float)loss;
    }
}

extern "C" void kernel_launch(void* const* d_in, const int* in_sizes, int n_in,
                              void* d_out, int out_size) {
    const float* X   = (const float*)d_in[0];
    const int*   lab = (const int*)d_in[1];
    float*       out = (float*)d_out;

    zero_kernel<<<1, 512>>>();
    pos_kernel<<<64, 64>>>(X, lab);
    dim3 g(64, 64);
    screen_kernel<<<g, 128>>>(X);
    stage2_kernel<<<256, 128>>>(X, lab);
    fallback_kernel<<<1024, 256>>>(X, lab);
    finalize_kernel<<<1, 256>>>(lab, out);
}

// round 3
// speedup vs baseline: 1.0482x; 1.0482x over previous
#include <cuda_runtime.h>
#include <cuda_bf16.h>
#include <math.h>

// ContrastiveLoss: N=8192 points, D=64, labels int32 in [0,8).
// loss = [ sum_{same-label,i!=j} d2  +  sum_{diff-label} max(1-d,0)^2 ] / (N*(N-1))
//
//   pos term: exact closed form per class: sum d2 = 2*(n_c*S2_c - |S1_c|^2)  (O(N*D))
//   neg term: nonzero only when d < 1. dot-form 8-dim partial distance is an exact
//             lower bound on d2 -> screen all pairs (register-blocked 4x, dot form),
//             inline-evaluate rare survivors on all 64 dims. No survivor list, no cap.

#define N_PTS 8192
#define NDIM  64
#define NCLS  8
#define TI    512     // i-rows per screen block (4 per thread)
#define TJ    128     // j-rows per screen block

__device__ float  g_h[N_PTS];                 // 0.5 * sum(x[0:8]^2) per row
__device__ float  g_p1[64 * NCLS * NDIM];     // per-block pos partial sums
__device__ float  g_p2[64 * NCLS * NDIM];     // per-block pos partial sum-of-squares
__device__ double g_neg;

// ---------------- K1: prep (pos partials + screen half-norms + zero g_neg) ----
// grid 64 x 64 threads. Block b: rows [b*128, b*128+128). Thread k = dimension.
__global__ void __launch_bounds__(64) prep_kernel(const float* __restrict__ X,
                                                  const int* __restrict__ lab) {
    int k  = threadIdx.x;
    int b  = blockIdx.x;
    int r0 = b * 128;
    if (b == 0 && k == 0) g_neg = 0.0;

    __shared__ int slab[128];
    for (int r = k; r < 128; r += 64) slab[r] = lab[r0 + r];
    __syncthreads();

    // half-norms of first 8 dims: 2 rows per thread
    const float4* Xv = (const float4*)X;
#pragma unroll
    for (int q = 0; q < 2; q++) {
        int r = r0 + k * 2 + q;
        float4 v0 = Xv[r * 16 + 0];
        float4 v1 = Xv[r * 16 + 1];
        float s = v0.x*v0.x + v0.y*v0.y + v0.z*v0.z + v0.w*v0.w
                + v1.x*v1.x + v1.y*v1.y + v1.z*v1.z + v1.w*v1.w;
        g_h[r] = 0.5f * s;
    }

    float a1[NCLS], a2[NCLS];
#pragma unroll
    for (int c = 0; c < NCLS; c++) { a1[c] = 0.0f; a2[c] = 0.0f; }
    for (int rr = 0; rr < 128; ++rr) {
        float v  = X[(r0 + rr) * NDIM + k];
        float v2 = v * v;
        int   c  = slab[rr];
#pragma unroll
        for (int cc = 0; cc < NCLS; cc++) {
            bool m = (cc == c);
            a1[cc] += m ? v  : 0.0f;
            a2[cc] += m ? v2 : 0.0f;
        }
    }
#pragma unroll
    for (int cc = 0; cc < NCLS; cc++) {
        g_p1[b * (NCLS * NDIM) + cc * NDIM + k] = a1[cc];
        g_p2[b * (NCLS * NDIM) + cc * NDIM + k] = a2[cc];
    }
}

// ---------------- rare path: exact 64-dim evaluation ----------------
__device__ __noinline__ void eval_pair(const float* __restrict__ X,
                                       const int* __restrict__ lab, int i, int j) {
    if (lab[i] == lab[j]) return;       // same-label handled in closed form
    const float4* xi = (const float4*)(X + i * NDIM);
    const float4* xj = (const float4*)(X + j * NDIM);
    float s = 0.0f;
#pragma unroll
    for (int q = 0; q < 16; q++) {
        float4 a = xi[q], b = xj[q];
        float d;
        d = a.x - b.x; s = fmaf(d, d, s);
        d = a.y - b.y; s = fmaf(d, d, s);
        d = a.z - b.z; s = fmaf(d, d, s);
        d = a.w - b.w; s = fmaf(d, d, s);
    }
    if (s < 1.0f) {
        float u = 1.0f - sqrtf(fmaxf(s, 0.0f));
        atomicAdd(&g_neg, 2.0 * (double)u * (double)u);   // unordered -> ordered pairs
    }
}

// ---------------- K2: screen (8-dim dot-form lower bound) + inline eval -------
// grid (64, 16), 128 threads. Block (bj,bi): i in [bi*512,+512), j in [bj*128,+128).
// Keep only blocks that can contain pairs with j > i:  bj >= 4*bi.
__global__ void __launch_bounds__(128) screen_kernel(const float* __restrict__ X,
                                                     const int* __restrict__ lab) {
    int bi = blockIdx.y, bj = blockIdx.x;
    if (bj < 4 * bi) return;
    int t = threadIdx.x;

    __shared__ float4 sj[TJ][2];
    __shared__ float  shj[TJ];
    const float4* Xv = (const float4*)X;

    int jr = bj * TJ + t;
    sj[t][0] = Xv[jr * 16 + 0];
    sj[t][1] = Xv[jr * 16 + 1];
    shj[t]   = g_h[jr];

    float4 a[4][2];
    float  ci[4];
    int    ib[4];
#pragma unroll
    for (int r = 0; r < 4; r++) {
        ib[r]   = bi * TI + r * 128 + t;
        a[r][0] = Xv[ib[r] * 16 + 0];
        a[r][1] = Xv[ib[r] * 16 + 1];
        ci[r]   = g_h[ib[r]] - 0.505f;   // pass <=> dot > ci + hj  <=> est d2_8 < 1.01
    }
    __syncthreads();

#pragma unroll 4
    for (int j = 0; j < TJ; ++j) {
        float4 b0 = sj[j][0];
        float4 b1 = sj[j][1];
        float  hj = shj[j];
        int    jg = bj * TJ + j;
#pragma unroll
        for (int r = 0; r < 4; r++) {
            float dot;
            dot = a[r][0].x * b0.x;
            dot = fmaf(a[r][0].y, b0.y, dot);
            dot = fmaf(a[r][0].z, b0.z, dot);
            dot = fmaf(a[r][0].w, b0.w, dot);
            dot = fmaf(a[r][1].x, b1.x, dot);
            dot = fmaf(a[r][1].y, b1.y, dot);
            dot = fmaf(a[r][1].z, b1.z, dot);
            dot = fmaf(a[r][1].w, b1.w, dot);
            if (dot > ci[r] + hj && jg > ib[r])
                eval_pair(X, lab, ib[r], jg);
        }
    }
}

// ---------------- K3: finalize ----------------
__global__ void __launch_bounds__(512) finalize_kernel(const int* __restrict__ lab,
                                                       float* __restrict__ out) {
    int t = threadIdx.x;                    // t = c*64 + k
    __shared__ int    hist[NCLS];
    __shared__ double red[512];

    if (t < NCLS) hist[t] = 0;
    __syncthreads();
    for (int r = t; r < N_PTS; r += 512) atomicAdd(&hist[lab[r]], 1);
    __syncthreads();

    int c = t >> 6;
    float S1 = 0.0f, S2 = 0.0f;
    for (int b = 0; b < 64; b++) {
        S1 += g_p1[b * 512 + t];
        S2 += g_p2[b * 512 + t];
    }
    red[t] = (double)hist[c] * (double)S2 - (double)S1 * (double)S1;
    __syncthreads();
    for (int s = 256; s > 0; s >>= 1) {
        if (t < s) red[t] += red[t + s];
        __syncthreads();
    }
    if (t == 0) {
        double pos  = 2.0 * red[0];
        double loss = (pos + g_neg) / ((double)N_PTS * (double)(N_PTS - 1));
        out[0] = (float)loss;
    }
}

extern "C" void kernel_launch(void* const* d_in, const int* in_sizes, int n_in,
                              void* d_out, int out_size) {
    const float* X   = (const float*)d_in[0];
    const int*   lab = (const int*)d_in[1];
    float*       out = (float*)d_out;

    prep_kernel<<<64, 64>>>(X, lab);
    dim3 g(64, 16);
    screen_kernel<<<g, 128>>>(X, lab);
    finalize_kernel<<<1, 512>>>(lab, out);
}

// round 4
// speedup vs baseline: 1.1414x; 1.0889x over previous
#include <cuda_runtime.h>
#include <cuda_bf16.h>
#include <math.h>

// ContrastiveLoss: N=8192 points, D=64, labels int32 in [0,8).
// loss = [ sum_{same-label,i!=j} d2  +  sum_{diff-label} max(1-d,0)^2 ] / (N*(N-1))
//
//   pos term: exact closed form per class: sum d2 = 2*(n_c*S2_c - |S1_c|^2)  (O(N*D))
//   neg term: nonzero only when d < 1. 8-dim partial distance (dot form) is an exact
//             lower bound on d2 -> screen all pairs, inline-evaluate rare survivors
//             on all 64 dims. No survivor list, no cap, no overflow path needed.

#define N_PTS 8192
#define NDIM  64
#define NCLS  8
#define PBLK  128     // prep blocks
#define PROWS 64      // rows per prep block
#define TI    512     // i-rows per screen block (4 per thread)
#define TJ    128     // j-rows per screen block

__device__ float  g_p1[PBLK * NCLS * NDIM];   // per-block pos partial sums
__device__ float  g_p2[PBLK * NCLS * NDIM];   // per-block pos partial sum-of-squares
__device__ double g_neg;

// ---------------- K1: prep (per-class partial sums, zero g_neg) ----------------
// grid PBLK x 64 threads. Block b: rows [b*64, b*64+64). Thread k = dimension.
__global__ void __launch_bounds__(64) prep_kernel(const float* __restrict__ X,
                                                  const int* __restrict__ lab) {
    int k  = threadIdx.x;
    int b  = blockIdx.x;
    int r0 = b * PROWS;
    if (b == 0 && k == 0) g_neg = 0.0;

    __shared__ int slab[PROWS];
    for (int r = k; r < PROWS; r += 64) slab[r] = lab[r0 + r];
    __syncthreads();

    float a1[NCLS], a2[NCLS];
#pragma unroll
    for (int c = 0; c < NCLS; c++) { a1[c] = 0.0f; a2[c] = 0.0f; }
#pragma unroll 4
    for (int rr = 0; rr < PROWS; ++rr) {
        float v  = X[(r0 + rr) * NDIM + k];
        float v2 = v * v;
        int   c  = slab[rr];
#pragma unroll
        for (int cc = 0; cc < NCLS; cc++) {
            bool m = (cc == c);
            a1[cc] += m ? v  : 0.0f;
            a2[cc] += m ? v2 : 0.0f;
        }
    }
#pragma unroll
    for (int cc = 0; cc < NCLS; cc++) {
        g_p1[b * (NCLS * NDIM) + cc * NDIM + k] = a1[cc];
        g_p2[b * (NCLS * NDIM) + cc * NDIM + k] = a2[cc];
    }
}

// ---------------- rare path: exact 64-dim evaluation ----------------
__device__ __noinline__ void eval_pair(const float* __restrict__ X,
                                       const int* __restrict__ lab, int i, int j) {
    if (lab[i] == lab[j]) return;       // same-label handled in closed form
    const float4* xi = (const float4*)(X + i * NDIM);
    const float4* xj = (const float4*)(X + j * NDIM);
    float s = 0.0f;
#pragma unroll
    for (int q = 0; q < 16; q++) {
        float4 a = xi[q], b = xj[q];
        float d;
        d = a.x - b.x; s = fmaf(d, d, s);
        d = a.y - b.y; s = fmaf(d, d, s);
        d = a.z - b.z; s = fmaf(d, d, s);
        d = a.w - b.w; s = fmaf(d, d, s);
    }
    if (s < 1.0f) {
        float u = 1.0f - sqrtf(fmaxf(s, 0.0f));
        atomicAdd(&g_neg, 2.0 * (double)u * (double)u);   // unordered -> ordered pairs
    }
}

__device__ __forceinline__ float half_norm8(float4 v0, float4 v1) {
    float s = v0.x * v0.x;
    s = fmaf(v0.y, v0.y, s);
    s = fmaf(v0.z, v0.z, s);
    s = fmaf(v0.w, v0.w, s);
    s = fmaf(v1.x, v1.x, s);
    s = fmaf(v1.y, v1.y, s);
    s = fmaf(v1.z, v1.z, s);
    s = fmaf(v1.w, v1.w, s);
    return 0.5f * s;
}

// ---------------- K2: screen (8-dim dot-form lower bound) + inline eval -------
// grid (64, 16), 128 threads. Block (bj,bi): i in [bi*512,+512), j in [bj*128,+128).
// Keep blocks that can contain j > i pairs: bj >= 4*bi. Blocks with bj >= 4*bi+4
// are fully off-diagonal -> skip the per-pair j>i test.
// Pass test: dot8 - hj > hi - 0.505  <=>  partial d2 over 8 dims < 1.01 (exact LB).
__global__ void __launch_bounds__(128) screen_kernel(const float* __restrict__ X,
                                                     const int* __restrict__ lab) {
    int bi = blockIdx.y, bj = blockIdx.x;
    if (bj < 4 * bi) return;
    int t = threadIdx.x;

    __shared__ float4 sj[TJ][2];
    __shared__ float  smhj[TJ];       // -hj
    const float4* Xv = (const float4*)X;

    int jr = bj * TJ + t;
    float4 j0 = Xv[jr * 16 + 0];
    float4 j1 = Xv[jr * 16 + 1];
    sj[t][0] = j0;
    sj[t][1] = j1;
    smhj[t]  = -half_norm8(j0, j1);

    float4 a[4][2];
    float  ci[4];
    int    ib[4];
#pragma unroll
    for (int r = 0; r < 4; r++) {
        ib[r]   = bi * TI + r * 128 + t;
        a[r][0] = Xv[ib[r] * 16 + 0];
        a[r][1] = Xv[ib[r] * 16 + 1];
        ci[r]   = half_norm8(a[r][0], a[r][1]) - 0.505f;
    }
    __syncthreads();

    bool diag = (bj < 4 * bi + 4);
    if (!diag) {
        // fully off-diagonal: every (i,j) here has j > i
#pragma unroll 4
        for (int j = 0; j < TJ; ++j) {
            float4 b0 = sj[j][0];
            float4 b1 = sj[j][1];
            float mhj = smhj[j];
#pragma unroll
            for (int r = 0; r < 4; r++) {
                float dot = fmaf(a[r][0].x, b0.x, mhj);
                dot = fmaf(a[r][0].y, b0.y, dot);
                dot = fmaf(a[r][0].z, b0.z, dot);
                dot = fmaf(a[r][0].w, b0.w, dot);
                dot = fmaf(a[r][1].x, b1.x, dot);
                dot = fmaf(a[r][1].y, b1.y, dot);
                dot = fmaf(a[r][1].z, b1.z, dot);
                dot = fmaf(a[r][1].w, b1.w, dot);
                if (dot > ci[r]) eval_pair(X, lab, ib[r], bj * TJ + j);
            }
        }
    } else {
#pragma unroll 4
        for (int j = 0; j < TJ; ++j) {
            float4 b0 = sj[j][0];
            float4 b1 = sj[j][1];
            float mhj = smhj[j];
            int    jg = bj * TJ + j;
#pragma unroll
            for (int r = 0; r < 4; r++) {
                float dot = fmaf(a[r][0].x, b0.x, mhj);
                dot = fmaf(a[r][0].y, b0.y, dot);
                dot = fmaf(a[r][0].z, b0.z, dot);
                dot = fmaf(a[r][0].w, b0.w, dot);
                dot = fmaf(a[r][1].x, b1.x, dot);
                dot = fmaf(a[r][1].y, b1.y, dot);
                dot = fmaf(a[r][1].z, b1.z, dot);
                dot = fmaf(a[r][1].w, b1.w, dot);
                if (dot > ci[r] && jg > ib[r]) eval_pair(X, lab, ib[r], jg);
            }
        }
    }
}

// ---------------- K3: finalize ----------------
__global__ void __launch_bounds__(512) finalize_kernel(const int* __restrict__ lab,
                                                       float* __restrict__ out) {
    int t = threadIdx.x;                    // t = c*64 + k
    __shared__ int    hist[NCLS];
    __shared__ double red[512];

    if (t < NCLS) hist[t] = 0;
    __syncthreads();
    for (int r = t; r < N_PTS; r += 512) atomicAdd(&hist[lab[r]], 1);
    __syncthreads();

    int c = t >> 6;
    float S1 = 0.0f, S2 = 0.0f;
#pragma unroll 4
    for (int b = 0; b < PBLK; b++) {
        S1 += g_p1[b * 512 + t];
        S2 += g_p2[b * 512 + t];
    }
    red[t] = (double)hist[c] * (double)S2 - (double)S1 * (double)S1;
    __syncthreads();
    for (int s = 256; s > 0; s >>= 1) {
        if (t < s) red[t] += red[t + s];
        __syncthreads();
    }
    if (t == 0) {
        double pos  = 2.0 * red[0];
        double loss = (pos + g_neg) / ((double)N_PTS * (double)(N_PTS - 1));
        out[0] = (float)loss;
    }
}

extern "C" void kernel_launch(void* const* d_in, const int* in_sizes, int n_in,
                              void* d_out, int out_size) {
    const float* X   = (const float*)d_in[0];
    const int*   lab = (const int*)d_in[1];
    float*       out = (float*)d_out;

    prep_kernel<<<PBLK, 64>>>(X, lab);
    dim3 g(64, 16);
    screen_kernel<<<g, 128>>>(X, lab);
    finalize_kernel<<<1, 512>>>(lab, out);
}